// round 1
// baseline (speedup 1.0000x reference)
#include <cuda_runtime.h>
#include <math.h>

#define IMG_H 512
#define IMG_W 512
#define N_IMG 32
#define WS 11
#define HALO 5
#define TS 32
#define TW (TS + 2*HALO)   // 42

struct Weights { float w[WS]; };

__device__ unsigned g_min_u;
__device__ unsigned g_max_u;

__device__ __forceinline__ unsigned encf(float f) {
    unsigned u = __float_as_uint(f);
    return (u & 0x80000000u) ? ~u : (u | 0x80000000u);
}
__device__ __forceinline__ float decf(unsigned u) {
    u = (u & 0x80000000u) ? (u & 0x7fffffffu) : ~u;
    return __uint_as_float(u);
}

__global__ void init_minmax_kernel() {
    g_min_u = 0xFFFFFFFFu;
    g_max_u = 0u;
}

__global__ void minmax_kernel(const float* __restrict__ x, int n4) {
    unsigned mn = 0xFFFFFFFFu, mx = 0u;
    const float4* x4 = (const float4*)x;
    for (int i = blockIdx.x * blockDim.x + threadIdx.x; i < n4;
         i += gridDim.x * blockDim.x) {
        float4 v = x4[i];
        unsigned e0 = encf(v.x), e1 = encf(v.y), e2 = encf(v.z), e3 = encf(v.w);
        mn = min(mn, min(min(e0, e1), min(e2, e3)));
        mx = max(mx, max(max(e0, e1), max(e2, e3)));
    }
    // warp reduce
    #pragma unroll
    for (int off = 16; off > 0; off >>= 1) {
        mn = min(mn, __shfl_xor_sync(0xFFFFFFFFu, mn, off));
        mx = max(mx, __shfl_xor_sync(0xFFFFFFFFu, mx, off));
    }
    __shared__ unsigned smn[8], smx[8];
    int wid = threadIdx.x >> 5, lid = threadIdx.x & 31;
    if (lid == 0) { smn[wid] = mn; smx[wid] = mx; }
    __syncthreads();
    if (threadIdx.x == 0) {
        unsigned bmn = smn[0], bmx = smx[0];
        int nw = blockDim.x >> 5;
        for (int i = 1; i < nw; i++) { bmn = min(bmn, smn[i]); bmx = max(bmx, smx[i]); }
        atomicMin(&g_min_u, bmn);
        atomicMax(&g_max_u, bmx);
    }
}

__global__ __launch_bounds__(256)
void ssim_kernel(const float* __restrict__ img1, const float* __restrict__ img2,
                 float* __restrict__ out, Weights wt) {
    __shared__ float s1[TW][TW];
    __shared__ float s2[TW][TW];
    __shared__ float h[5][TW][TS];

    const int n = blockIdx.z;
    const int x0 = blockIdx.x * TS;
    const int y0 = blockIdx.y * TS;
    const int tid = threadIdx.x;

    const float* p1 = img1 + (size_t)n * IMG_H * IMG_W;
    const float* p2 = img2 + (size_t)n * IMG_H * IMG_W;

    // ---- load raw tiles with halo (zero-pad at borders) ----
    for (int idx = tid; idx < TW * TW; idx += 256) {
        int r = idx / TW, c = idx % TW;
        int gy = y0 + r - HALO, gx = x0 + c - HALO;
        bool in = (gy >= 0) & (gy < IMG_H) & (gx >= 0) & (gx < IMG_W);
        float a = 0.f, b = 0.f;
        if (in) {
            size_t o = (size_t)gy * IMG_W + gx;
            a = p1[o];
            b = p2[o];
        }
        s1[r][c] = a;
        s2[r][c] = b;
    }
    __syncthreads();

    // ---- horizontal pass: 5 fields (a, b, a^2, b^2, ab) ----
    for (int idx = tid; idx < TW * TS; idx += 256) {
        int r = idx / TS, c = idx % TS;
        float f0 = 0.f, f1 = 0.f, f2 = 0.f, f3 = 0.f, f4 = 0.f;
        #pragma unroll
        for (int k = 0; k < WS; k++) {
            float wk = wt.w[k];
            float a = s1[r][c + k];
            float b = s2[r][c + k];
            f0 = fmaf(wk, a, f0);
            f1 = fmaf(wk, b, f1);
            f2 = fmaf(wk * a, a, f2);
            f3 = fmaf(wk * b, b, f3);
            f4 = fmaf(wk * a, b, f4);
        }
        h[0][r][c] = f0;
        h[1][r][c] = f1;
        h[2][r][c] = f2;
        h[3][r][c] = f3;
        h[4][r][c] = f4;
    }
    __syncthreads();

    // ---- constants from global min/max of img1 ----
    float vmin = decf(g_min_u);
    float vmax = decf(g_max_u);
    float L = vmax - vmin;
    if (L == 0.f) L = 5.f;
    float C1 = (0.01f * L) * (0.01f * L);
    float C2 = (0.03f * L) * (0.03f * L);

    // ---- vertical pass + SSIM formula; 4 output rows per thread ----
    const int tx = tid & 31;
    const int ty0 = tid >> 5;   // 0..7
    float* po = out + (size_t)n * IMG_H * IMG_W;

    #pragma unroll
    for (int rr = 0; rr < 4; rr++) {
        int ty = ty0 + rr * 8;
        float m1 = 0.f, m2 = 0.f, q1 = 0.f, q2 = 0.f, q12 = 0.f;
        #pragma unroll
        for (int k = 0; k < WS; k++) {
            float wk = wt.w[k];
            m1  = fmaf(wk, h[0][ty + k][tx], m1);
            m2  = fmaf(wk, h[1][ty + k][tx], m2);
            q1  = fmaf(wk, h[2][ty + k][tx], q1);
            q2  = fmaf(wk, h[3][ty + k][tx], q2);
            q12 = fmaf(wk, h[4][ty + k][tx], q12);
        }
        float mu1_sq = m1 * m1;
        float mu2_sq = m2 * m2;
        float mu1mu2 = m1 * m2;
        float sig1 = q1 - mu1_sq;
        float sig2 = q2 - mu2_sq;
        float sig12 = q12 - mu1mu2;
        float num = (2.f * mu1mu2 + C1) * (2.f * sig12 + C2);
        float den = (mu1_sq + mu2_sq + C1) * (sig1 + sig2 + C2);
        po[(size_t)(y0 + ty) * IMG_W + (x0 + tx)] = num / den;
    }
}

extern "C" void kernel_launch(void* const* d_in, const int* in_sizes, int n_in,
                              void* d_out, int out_size) {
    const float* img1 = (const float*)d_in[0];
    const float* img2 = (const float*)d_in[1];
    float* out = (float*)d_out;

    // Gaussian taps, center at ws/2 = 5.5 (asymmetric, matching torch quirk)
    Weights wt;
    {
        double g[WS], s = 0.0;
        for (int i = 0; i < WS; i++) {
            double d = (double)i - (double)WS / 2.0;
            g[i] = exp(-(d * d) / (2.0 * 1.5 * 1.5));
            s += g[i];
        }
        for (int i = 0; i < WS; i++) wt.w[i] = (float)(g[i] / s);
    }

    int n_elems = N_IMG * IMG_H * IMG_W;

    init_minmax_kernel<<<1, 1>>>();
    minmax_kernel<<<1024, 256>>>(img1, n_elems / 4);

    dim3 grid(IMG_W / TS, IMG_H / TS, N_IMG);
    ssim_kernel<<<grid, 256>>>(img1, img2, out, wt);
}

// round 3
// speedup vs baseline: 1.2068x; 1.2068x over previous
#include <cuda_runtime.h>
#include <math.h>

#define IMG_H 512
#define IMG_W 512
#define N_IMG 32
#define WS 11
#define HALO 5
#define TS 32
#define TW (TS + 2*HALO)   // 42
#define SPITCH 44          // padded row pitch for s1/s2 (16B-aligned float4 rows)
#define NPART 512          // minmax partial blocks

// Gaussian taps, center at ws/2 = 5.5 (torch quirk): w[k] = w[11-k] for k>=1
__device__ __constant__ const float Wc[WS] = {
    0.00032030f, 0.00295560f, 0.01748760f, 0.06634250f, 0.16137300f,
    0.25168080f, 0.25168080f, 0.16137300f, 0.06634250f, 0.01748760f,
    0.00295560f
};
// compile-time copy for immediate-form FFMA
#define W0 0.00032030f
#define W1 0.00295560f
#define W2 0.01748760f
#define W3 0.06634250f
#define W4 0.16137300f
#define W5 0.25168080f
__device__ __forceinline__ float wk_of(int k) {
    // resolved at compile time under full unroll
    switch (k) {
        case 0: return W0; case 1: return W1; case 2: return W2;
        case 3: return W3; case 4: return W4; case 5: return W5;
        case 6: return W5; case 7: return W4; case 8: return W3;
        case 9: return W2; default: return W1;
    }
}

__device__ unsigned g_pmin[NPART];
__device__ unsigned g_pmax[NPART];

__device__ __forceinline__ unsigned encf(float f) {
    unsigned u = __float_as_uint(f);
    return (u & 0x80000000u) ? ~u : (u | 0x80000000u);
}
__device__ __forceinline__ float decf(unsigned u) {
    u = (u & 0x80000000u) ? (u & 0x7fffffffu) : ~u;
    return __uint_as_float(u);
}

__global__ __launch_bounds__(256)
void minmax_kernel(const float* __restrict__ x, int n4) {
    unsigned mn = 0xFFFFFFFFu, mx = 0u;
    const float4* x4 = (const float4*)x;
    for (int i = blockIdx.x * blockDim.x + threadIdx.x; i < n4;
         i += gridDim.x * blockDim.x) {
        float4 v = x4[i];
        unsigned e0 = encf(v.x), e1 = encf(v.y), e2 = encf(v.z), e3 = encf(v.w);
        mn = min(mn, min(min(e0, e1), min(e2, e3)));
        mx = max(mx, max(max(e0, e1), max(e2, e3)));
    }
    #pragma unroll
    for (int off = 16; off > 0; off >>= 1) {
        mn = min(mn, __shfl_xor_sync(0xFFFFFFFFu, mn, off));
        mx = max(mx, __shfl_xor_sync(0xFFFFFFFFu, mx, off));
    }
    __shared__ unsigned smn[8], smx[8];
    int wid = threadIdx.x >> 5, lid = threadIdx.x & 31;
    if (lid == 0) { smn[wid] = mn; smx[wid] = mx; }
    __syncthreads();
    if (threadIdx.x == 0) {
        unsigned bmn = smn[0], bmx = smx[0];
        #pragma unroll
        for (int i = 1; i < 8; i++) { bmn = min(bmn, smn[i]); bmx = max(bmx, smx[i]); }
        g_pmin[blockIdx.x] = bmn;   // unconditional write -> no init kernel needed
        g_pmax[blockIdx.x] = bmx;
    }
}

__global__ __launch_bounds__(256)
void ssim_kernel(const float* __restrict__ img1, const float* __restrict__ img2,
                 float* __restrict__ out) {
    __shared__ float s1[TW][SPITCH];
    __shared__ float s2[TW][SPITCH];
    __shared__ float h[5][TW][TS];
    __shared__ unsigned red_mn[8], red_mx[8];

    const int n = blockIdx.z;
    const int x0 = blockIdx.x * TS;
    const int y0 = blockIdx.y * TS;
    const int tid = threadIdx.x;

    // ---- global min/max: reduce 512 L2-hot partials ----
    {
        unsigned mn = min(g_pmin[tid], g_pmin[tid + 256]);
        unsigned mx = max(g_pmax[tid], g_pmax[tid + 256]);
        #pragma unroll
        for (int off = 16; off > 0; off >>= 1) {
            mn = min(mn, __shfl_xor_sync(0xFFFFFFFFu, mn, off));
            mx = max(mx, __shfl_xor_sync(0xFFFFFFFFu, mx, off));
        }
        if ((tid & 31) == 0) { red_mn[tid >> 5] = mn; red_mx[tid >> 5] = mx; }
    }

    const float* p1 = img1 + (size_t)n * IMG_H * IMG_W;
    const float* p2 = img2 + (size_t)n * IMG_H * IMG_W;

    // ---- load raw tiles with halo (zero-pad at borders) ----
    for (int idx = tid; idx < TW * TW; idx += 256) {
        int r = idx / TW, c = idx - r * TW;
        int gy = y0 + r - HALO, gx = x0 + c - HALO;
        bool in = (gy >= 0) & (gy < IMG_H) & (gx >= 0) & (gx < IMG_W);
        float a = 0.f, b = 0.f;
        if (in) {
            size_t o = (size_t)gy * IMG_W + gx;
            a = __ldg(p1 + o);
            b = __ldg(p2 + o);
        }
        s1[r][c] = a;
        s2[r][c] = b;
    }
    __syncthreads();

    // ---- horizontal pass: 4 adjacent outputs per item, 5 fields ----
    // items: r in [0,TW), q in [0,8) -> c0 = 4q ; TW*8 = 336 items
    for (int item = tid; item < TW * 8; item += 256) {
        int r = item >> 3;
        int c0 = (item & 7) << 2;
        // load 16 positions (need 14) via float4
        float A[16], B[16];
        #pragma unroll
        for (int j = 0; j < 4; j++) {
            float4 va = *(const float4*)&s1[r][c0 + 4 * j];
            float4 vb = *(const float4*)&s2[r][c0 + 4 * j];
            A[4*j+0] = va.x; A[4*j+1] = va.y; A[4*j+2] = va.z; A[4*j+3] = va.w;
            B[4*j+0] = vb.x; B[4*j+1] = vb.y; B[4*j+2] = vb.z; B[4*j+3] = vb.w;
        }
        float f0[4] = {0,0,0,0}, f1[4] = {0,0,0,0}, f2[4] = {0,0,0,0};
        float f3[4] = {0,0,0,0}, f4[4] = {0,0,0,0};
        #pragma unroll
        for (int i = 0; i < 14; i++) {
            float a = A[i], b = B[i];
            float p2v = a * a, q2v = b * b, pqv = a * b;
            #pragma unroll
            for (int j = 0; j < 4; j++) {
                int k = i - j;
                if (k >= 0 && k < WS) {
                    float wk = wk_of(k);
                    f0[j] = fmaf(wk, a,   f0[j]);
                    f1[j] = fmaf(wk, b,   f1[j]);
                    f2[j] = fmaf(wk, p2v, f2[j]);
                    f3[j] = fmaf(wk, q2v, f3[j]);
                    f4[j] = fmaf(wk, pqv, f4[j]);
                }
            }
        }
        *(float4*)&h[0][r][c0] = make_float4(f0[0], f0[1], f0[2], f0[3]);
        *(float4*)&h[1][r][c0] = make_float4(f1[0], f1[1], f1[2], f1[3]);
        *(float4*)&h[2][r][c0] = make_float4(f2[0], f2[1], f2[2], f2[3]);
        *(float4*)&h[3][r][c0] = make_float4(f3[0], f3[1], f3[2], f3[3]);
        *(float4*)&h[4][r][c0] = make_float4(f4[0], f4[1], f4[2], f4[3]);
    }
    __syncthreads();

    // ---- constants from reduced min/max ----
    float C1, C2;
    {
        unsigned bmn = red_mn[0], bmx = red_mx[0];
        #pragma unroll
        for (int i = 1; i < 8; i++) { bmn = min(bmn, red_mn[i]); bmx = max(bmx, red_mx[i]); }
        float L = decf(bmx) - decf(bmn);
        if (L == 0.f) L = 5.f;
        C1 = (0.01f * L) * (0.01f * L);
        C2 = (0.03f * L) * (0.03f * L);
    }

    // ---- vertical pass: 4 adjacent output rows per thread + SSIM formula ----
    const int tx = tid & 31;
    const int ty0 = (tid >> 5) << 2;   // 0,4,...,28
    float* po = out + (size_t)n * IMG_H * IMG_W;

    float m1[4] = {0,0,0,0}, m2[4] = {0,0,0,0};
    float q1[4] = {0,0,0,0}, q2a[4] = {0,0,0,0}, q12[4] = {0,0,0,0};
    #pragma unroll
    for (int i = 0; i < 14; i++) {
        float v0 = h[0][ty0 + i][tx];
        float v1 = h[1][ty0 + i][tx];
        float v2 = h[2][ty0 + i][tx];
        float v3 = h[3][ty0 + i][tx];
        float v4 = h[4][ty0 + i][tx];
        #pragma unroll
        for (int j = 0; j < 4; j++) {
            int k = i - j;
            if (k >= 0 && k < WS) {
                float wk = wk_of(k);
                m1[j]  = fmaf(wk, v0, m1[j]);
                m2[j]  = fmaf(wk, v1, m2[j]);
                q1[j]  = fmaf(wk, v2, q1[j]);
                q2a[j] = fmaf(wk, v3, q2a[j]);
                q12[j] = fmaf(wk, v4, q12[j]);
            }
        }
    }
    #pragma unroll
    for (int j = 0; j < 4; j++) {
        float mu1_sq = m1[j] * m1[j];
        float mu2_sq = m2[j] * m2[j];
        float mu1mu2 = m1[j] * m2[j];
        float sig1  = q1[j]  - mu1_sq;
        float sig2  = q2a[j] - mu2_sq;
        float sig12 = q12[j] - mu1mu2;
        float num = (2.f * mu1mu2 + C1) * (2.f * sig12 + C2);
        float den = (mu1_sq + mu2_sq + C1) * (sig1 + sig2 + C2);
        po[(size_t)(y0 + ty0 + j) * IMG_W + (x0 + tx)] = __fdividef(num, den);
    }
}

extern "C" void kernel_launch(void* const* d_in, const int* in_sizes, int n_in,
                              void* d_out, int out_size) {
    const float* img1 = (const float*)d_in[0];
    const float* img2 = (const float*)d_in[1];
    float* out = (float*)d_out;

    int n_elems = N_IMG * IMG_H * IMG_W;
    minmax_kernel<<<NPART, 256>>>(img1, n_elems / 4);

    dim3 grid(IMG_W / TS, IMG_H / TS, N_IMG);
    ssim_kernel<<<grid, 256>>>(img1, img2, out);
}